// round 11
// baseline (speedup 1.0000x reference)
#include <cuda_runtime.h>
#include <cstdint>
#include <cstddef>
#include <math.h>

#define D_DIM 2048
#define E_DIM 64
#define TM    128
#define BK    32
#define KHALF 1024
#define NCH   (KHALF / BK)   // 32 chunks per k-half
#define NTHREADS 512
#define TOPK  8

typedef unsigned long long u64;

#define A_BYTES  (2 * 2 * BK * TM * 4)          // 65536
#define BD_OFF   A_BYTES
#define SMEM_BYTES (A_BYTES + 2 * 2 * BK * E_DIM * 8)  // 131072

// Packed dual ops (Blackwell f32x2)
__device__ __forceinline__ u64 ffma2(u64 a, u64 b, u64 c) {
    u64 d;
    asm("fma.rn.f32x2 %0, %1, %2, %3;" : "=l"(d) : "l"(a), "l"(b), "l"(c));
    return d;
}
__device__ __forceinline__ u64 fmul2(u64 a, u64 b) {
    u64 d;
    asm("mul.rn.f32x2 %0, %1, %2;" : "=l"(d) : "l"(a), "l"(b));
    return d;
}
__device__ __forceinline__ u64 fadd2(u64 a, u64 b) {
    u64 d;
    asm("add.rn.f32x2 %0, %1, %2;" : "=l"(d) : "l"(a), "l"(b));
    return d;
}
__device__ __forceinline__ u64 dup_f32(float v) {
    unsigned int u = __float_as_uint(v);
    return ((u64)u << 32) | (u64)u;
}

__global__ __launch_bounds__(NTHREADS, 1)
void router_gemm_softmax_topk(const float* __restrict__ h,
                              const float* __restrict__ W,
                              const float* __restrict__ cal_scale,
                              const float* __restrict__ cal_bias,
                              float* __restrict__ out,
                              int T) {
    extern __shared__ char smraw[];
    // A[half][buf][k][slot] : token slot order = (j>=4 ? 64:0) + 4*(t>>3) + (t&3)
    float (*A)[2][BK][TM]    = reinterpret_cast<float (*)[2][BK][TM]>(smraw);
    u64   (*Bd)[2][BK][E_DIM] = reinterpret_cast<u64 (*)[2][BK][E_DIM]>(smraw + BD_OFF);
    // P[half][token][expert] — reuses the tile region after the mainloop
    float (*P)[TM][E_DIM + 1] = reinterpret_cast<float (*)[TM][E_DIM + 1]>(smraw);

    const int tid  = threadIdx.x;
    const int half = tid >> 8;    // k-half: 0 or 1
    const int ht   = tid & 255;
    const int s    = ht & 15;     // token group: tokens 8s..8s+7
    const int eg   = ht >> 4;     // expert group 0..15: experts 4eg..4eg+3
    const int t0   = blockIdx.x * TM;

    // load roles
    const int r    = ht & 127;    // token row for A
    const int cseg = ht >> 7;     // which 16-k segment of the chunk
    const int e    = ht & 63;     // expert row for B
    const int kq   = ht >> 6;     // which 8-k segment (0..3)

    const float* hrow = h + (size_t)(t0 + r) * D_DIM + half * KHALF + cseg * 16;
    const float* wrow = W + (size_t)e * D_DIM + half * KHALF + kq * 8;

    const int slotr = ((r & 4) ? 64 : 0) + 4 * (r >> 3) + (r & 3);

    // accumulators: 4 token-pairs x 4 experts (this k-half)
    u64 acc[4][4];
#pragma unroll
    for (int j = 0; j < 4; j++)
#pragma unroll
        for (int i = 0; i < 4; i++) acc[j][i] = 0ULL;

    float4 a4[4];   // 16 k of this thread's token row
    float4 b4[2];   // 8 k of this thread's expert row

    auto ldg_chunk = [&](int c) {
        const float4* ap = reinterpret_cast<const float4*>(hrow + c * BK);
#pragma unroll
        for (int q = 0; q < 4; q++) a4[q] = ap[q];
        const float4* bp = reinterpret_cast<const float4*>(wrow + c * BK);
        b4[0] = bp[0];
        b4[1] = bp[1];
    };

    auto sts_chunk = [&](int buf) {
#pragma unroll
        for (int q = 0; q < 4; q++) {
            int kb = cseg * 16 + 4 * q;
            A[half][buf][kb + 0][slotr] = a4[q].x;
            A[half][buf][kb + 1][slotr] = a4[q].y;
            A[half][buf][kb + 2][slotr] = a4[q].z;
            A[half][buf][kb + 3][slotr] = a4[q].w;
        }
#pragma unroll
        for (int q = 0; q < 2; q++) {
            int kb = kq * 8 + 4 * q;
            Bd[half][buf][kb + 0][e] = dup_f32(q ? b4[1].x : b4[0].x);
            Bd[half][buf][kb + 1][e] = dup_f32(q ? b4[1].y : b4[0].y);
            Bd[half][buf][kb + 2][e] = dup_f32(q ? b4[1].z : b4[0].z);
            Bd[half][buf][kb + 3][e] = dup_f32(q ? b4[1].w : b4[0].w);
        }
    };

    // prologue
    ldg_chunk(0);
    sts_chunk(0);
    __syncthreads();

    for (int c = 0; c < NCH; c++) {
        const int buf = c & 1;
        if (c + 1 < NCH) ldg_chunk(c + 1);

        // level-1: plain 32-deep FMA2 chain per accumulator
        u64 y[4][4];
#pragma unroll
        for (int k = 0; k < BK; k++) {
            ulonglong2 aA = *reinterpret_cast<const ulonglong2*>(
                &A[half][buf][k][4 * s]);
            ulonglong2 aB = *reinterpret_cast<const ulonglong2*>(
                &A[half][buf][k][64 + 4 * s]);
            u64 a[4] = {aA.x, aA.y, aB.x, aB.y};
            ulonglong2 b0 = *reinterpret_cast<const ulonglong2*>(
                &Bd[half][buf][k][4 * eg]);
            ulonglong2 b1 = *reinterpret_cast<const ulonglong2*>(
                &Bd[half][buf][k][4 * eg + 2]);
            u64 bd[4] = {b0.x, b0.y, b1.x, b1.y};
            if (k == 0) {
#pragma unroll
                for (int j = 0; j < 4; j++)
#pragma unroll
                    for (int i = 0; i < 4; i++)
                        y[j][i] = fmul2(a[j], bd[i]);
            } else {
#pragma unroll
                for (int j = 0; j < 4; j++)
#pragma unroll
                    for (int i = 0; i < 4; i++)
                        y[j][i] = ffma2(a[j], bd[i], y[j][i]);
            }
        }
        // level-2 cascade
#pragma unroll
        for (int j = 0; j < 4; j++)
#pragma unroll
            for (int i = 0; i < 4; i++)
                acc[j][i] = fadd2(acc[j][i], y[j][i]);

        if (c + 1 < NCH) sts_chunk(buf ^ 1);
        __syncthreads();
    }

    // ---- dump raw half-partials (tile region is dead now) ----
#pragma unroll
    for (int j = 0; j < 4; j++) {
        int tA = 8 * s + 2 * j;   // pair j -> tokens tA, tA+1
#pragma unroll
        for (int i = 0; i < 4; i++) {
            u64 v = acc[j][i];
            P[half][tA + 0][4 * eg + i] =
                __uint_as_float((unsigned int)(v & 0xffffffffULL));
            P[half][tA + 1][4 * eg + i] =
                __uint_as_float((unsigned int)(v >> 32));
        }
    }
    __syncthreads();

    // ---- per-token: combine halves, calibrate, softmax + top-8 ----
    if (tid < TM) {
        const int t = tid;
        const float* r1 = P[1][t];
        float* row = P[0][t];
#pragma unroll 8
        for (int ee = 0; ee < E_DIM; ee++)
            row[ee] = fmaf(row[ee] + r1[ee], cal_scale[ee], cal_bias[ee]);

        float m = row[0];
#pragma unroll 8
        for (int ee = 1; ee < E_DIM; ee++) m = fmaxf(m, row[ee]);
        float ssum = 0.0f;
#pragma unroll 8
        for (int ee = 0; ee < E_DIM; ee++) {
            float p = expf(row[ee] - m);
            row[ee] = p;
            ssum += p;
        }
        float inv = 1.0f / ssum;
        float* oprob = out + (size_t)(t0 + t) * E_DIM;
#pragma unroll 8
        for (int ee = 0; ee < E_DIM; ee++) {
            float p = row[ee] * inv;
            row[ee] = p;
            oprob[ee] = p;
        }

        const size_t base_w = (size_t)T * E_DIM;
        const size_t base_i = base_w + (size_t)T * TOPK;
        u64 used = 0ULL;
#pragma unroll
        for (int rr = 0; rr < TOPK; rr++) {
            float bv = -1.0f;
            int   bi = 0;
            for (int ee = 0; ee < E_DIM; ee++) {
                bool ok = !((used >> ee) & 1ULL);
                float p = row[ee];
                if (ok && p > bv) { bv = p; bi = ee; }
            }
            used |= 1ULL << bi;
            out[base_w + (size_t)(t0 + t) * TOPK + rr] = bv;
            out[base_i + (size_t)(t0 + t) * TOPK + rr] = (float)bi;
        }
    }
}

extern "C" void kernel_launch(void* const* d_in, const int* in_sizes, int n_in,
                              void* d_out, int out_size) {
    const float* h  = (const float*)d_in[0];
    const float* W  = (const float*)d_in[1];
    const float* cs = (const float*)d_in[2];
    const float* cb = (const float*)d_in[3];
    float* out = (float*)d_out;

    cudaFuncSetAttribute(router_gemm_softmax_topk,
                         cudaFuncAttributeMaxDynamicSharedMemorySize, SMEM_BYTES);

    int T  = in_sizes[0] / D_DIM;   // 16384
    int nb = T / TM;                // 128 blocks
    router_gemm_softmax_topk<<<nb, NTHREADS, SMEM_BYTES>>>(h, W, cs, cb, out, T);
}

// round 12
// speedup vs baseline: 1.1659x; 1.1659x over previous
#include <cuda_runtime.h>
#include <cstdint>
#include <cstddef>
#include <math.h>

#define D_DIM 2048
#define E_DIM 64
#define TM    128
#define BK    32
#define KHALF 1024
#define NCH   (KHALF / BK)   // 32 chunks per k-half
#define NTHREADS 256
#define TOPK  8

typedef unsigned long long u64;

// smem layout: A[2][2][BK][TM] (64KB) then B[2][2][BK][E_DIM] (32KB); P unions base
#define A_BYTES    (2 * 2 * BK * TM * 4)            // 65536
#define B_OFF      A_BYTES
#define SMEM_BYTES (A_BYTES + 2 * 2 * BK * E_DIM * 4)  // 98304

// Packed dual ops (Blackwell f32x2)
__device__ __forceinline__ u64 ffma2(u64 a, u64 b, u64 c) {
    u64 d;
    asm("fma.rn.f32x2 %0, %1, %2, %3;" : "=l"(d) : "l"(a), "l"(b), "l"(c));
    return d;
}
__device__ __forceinline__ u64 fmul2(u64 a, u64 b) {
    u64 d;
    asm("mul.rn.f32x2 %0, %1, %2;" : "=l"(d) : "l"(a), "l"(b));
    return d;
}
__device__ __forceinline__ u64 fadd2(u64 a, u64 b) {
    u64 d;
    asm("add.rn.f32x2 %0, %1, %2;" : "=l"(d) : "l"(a), "l"(b));
    return d;
}
__device__ __forceinline__ u64 dup_f32(float v) {
    unsigned int u = __float_as_uint(v);
    return ((u64)u << 32) | (u64)u;
}

__global__ __launch_bounds__(NTHREADS, 1)
void router_gemm_softmax_topk(const float* __restrict__ h,
                              const float* __restrict__ W,
                              const float* __restrict__ cal_scale,
                              const float* __restrict__ cal_bias,
                              float* __restrict__ out,
                              int T) {
    extern __shared__ char smraw[];
    float (*A)[2][BK][TM]     = reinterpret_cast<float (*)[2][BK][TM]>(smraw);
    float (*B)[2][BK][E_DIM]  = reinterpret_cast<float (*)[2][BK][E_DIM]>(smraw + B_OFF);
    float (*P)[TM][E_DIM + 1] = reinterpret_cast<float (*)[TM][E_DIM + 1]>(smraw);

    const int tid  = threadIdx.x;
    const int half = tid >> 7;    // k-half: warps 0-3 -> 0, warps 4-7 -> 1
    const int ht   = tid & 127;
    const int s    = ht & 15;     // token slot: tokens 8s..8s+7
    const int eg   = ht >> 4;     // expert group 0..7: experts 8eg..8eg+7
    const int t0   = blockIdx.x * TM;

    // load roles (within the half's 128 threads)
    const int e    = ht & 63;     // expert row for B
    const int kseg = ht >> 6;     // 16-wide k-segment of the chunk (0/1)

    const float* hrow = h + (size_t)(t0 + ht) * D_DIM + half * KHALF;      // token row, full BK
    const float* wrow = W + (size_t)e * D_DIM + half * KHALF + 16 * kseg;  // expert row, 16 k

    // accumulators: 4 token-pairs x 8 experts (this k-half)
    u64 acc[4][8];
#pragma unroll
    for (int j = 0; j < 4; j++)
#pragma unroll
        for (int i = 0; i < 8; i++) acc[j][i] = 0ULL;

    float4 a4[8];   // 32 k of this thread's token row
    float4 b4[4];   // 16 k of this thread's expert row

    auto ldg_chunk = [&](int c) {
        const float4* ap = reinterpret_cast<const float4*>(hrow + c * BK);
#pragma unroll
        for (int q = 0; q < 8; q++) a4[q] = ap[q];
        const float4* bp = reinterpret_cast<const float4*>(wrow + c * BK);
#pragma unroll
        for (int q = 0; q < 4; q++) b4[q] = bp[q];
    };

    auto sts_chunk = [&](int buf) {
#pragma unroll
        for (int q = 0; q < 8; q++) {
            int kb = 4 * q;
            A[half][buf][kb + 0][ht] = a4[q].x;
            A[half][buf][kb + 1][ht] = a4[q].y;
            A[half][buf][kb + 2][ht] = a4[q].z;
            A[half][buf][kb + 3][ht] = a4[q].w;
        }
#pragma unroll
        for (int q = 0; q < 4; q++) {
            int kb = 16 * kseg + 4 * q;
            B[half][buf][kb + 0][e] = b4[q].x;
            B[half][buf][kb + 1][e] = b4[q].y;
            B[half][buf][kb + 2][e] = b4[q].z;
            B[half][buf][kb + 3][e] = b4[q].w;
        }
    };

    // prologue
    ldg_chunk(0);
    sts_chunk(0);
    __syncthreads();

    for (int c = 0; c < NCH; c++) {
        const int buf = c & 1;
        if (c + 1 < NCH) ldg_chunk(c + 1);

        // level-1: plain 32-deep FMA2 chain per accumulator (chunk partial)
        u64 y[4][8];
#pragma unroll
        for (int k = 0; k < BK; k++) {
            ulonglong2 aA = *reinterpret_cast<const ulonglong2*>(
                &A[half][buf][k][8 * s]);
            ulonglong2 aB = *reinterpret_cast<const ulonglong2*>(
                &A[half][buf][k][8 * s + 4]);
            u64 a[4] = {aA.x, aA.y, aB.x, aB.y};
            float4 bf0 = *reinterpret_cast<const float4*>(
                &B[half][buf][k][8 * eg]);
            float4 bf1 = *reinterpret_cast<const float4*>(
                &B[half][buf][k][8 * eg + 4]);
            u64 bd[8] = {dup_f32(bf0.x), dup_f32(bf0.y),
                         dup_f32(bf0.z), dup_f32(bf0.w),
                         dup_f32(bf1.x), dup_f32(bf1.y),
                         dup_f32(bf1.z), dup_f32(bf1.w)};
            if (k == 0) {
#pragma unroll
                for (int j = 0; j < 4; j++)
#pragma unroll
                    for (int i = 0; i < 8; i++)
                        y[j][i] = fmul2(a[j], bd[i]);
            } else {
#pragma unroll
                for (int j = 0; j < 4; j++)
#pragma unroll
                    for (int i = 0; i < 8; i++)
                        y[j][i] = ffma2(a[j], bd[i], y[j][i]);
            }
        }
        // level-2 cascade
#pragma unroll
        for (int j = 0; j < 4; j++)
#pragma unroll
            for (int i = 0; i < 8; i++)
                acc[j][i] = fadd2(acc[j][i], y[j][i]);

        if (c + 1 < NCH) sts_chunk(buf ^ 1);   // other buffer: safe vs current reads
        __syncthreads();
    }

    // ---- dump raw half-partials (tile region is dead after last sync) ----
#pragma unroll
    for (int j = 0; j < 4; j++) {
        int tA = 8 * s + 2 * j;   // pair j -> tokens tA, tA+1
#pragma unroll
        for (int i = 0; i < 8; i++) {
            u64 v = acc[j][i];
            P[half][tA + 0][8 * eg + i] =
                __uint_as_float((unsigned int)(v & 0xffffffffULL));
            P[half][tA + 1][8 * eg + i] =
                __uint_as_float((unsigned int)(v >> 32));
        }
    }
    __syncthreads();

    // ---- per-token: combine halves, calibrate, softmax + top-8 ----
    if (tid < TM) {
        const int t = tid;
        const float* r1 = P[1][t];
        float* row = P[0][t];
#pragma unroll 8
        for (int ee = 0; ee < E_DIM; ee++)
            row[ee] = fmaf(row[ee] + r1[ee], cal_scale[ee], cal_bias[ee]);

        float m = row[0];
#pragma unroll 8
        for (int ee = 1; ee < E_DIM; ee++) m = fmaxf(m, row[ee]);
        float ssum = 0.0f;
#pragma unroll 8
        for (int ee = 0; ee < E_DIM; ee++) {
            float p = expf(row[ee] - m);
            row[ee] = p;
            ssum += p;
        }
        float inv = 1.0f / ssum;
        float* oprob = out + (size_t)(t0 + t) * E_DIM;
#pragma unroll 8
        for (int ee = 0; ee < E_DIM; ee++) {
            float p = row[ee] * inv;
            row[ee] = p;
            oprob[ee] = p;
        }

        const size_t base_w = (size_t)T * E_DIM;
        const size_t base_i = base_w + (size_t)T * TOPK;
        u64 used = 0ULL;
#pragma unroll
        for (int rr = 0; rr < TOPK; rr++) {
            float bv = -1.0f;
            int   bi = 0;
            for (int ee = 0; ee < E_DIM; ee++) {
                bool ok = !((used >> ee) & 1ULL);
                float p = row[ee];
                if (ok && p > bv) { bv = p; bi = ee; }
            }
            used |= 1ULL << bi;
            out[base_w + (size_t)(t0 + t) * TOPK + rr] = bv;
            out[base_i + (size_t)(t0 + t) * TOPK + rr] = (float)bi;
        }
    }
}

extern "C" void kernel_launch(void* const* d_in, const int* in_sizes, int n_in,
                              void* d_out, int out_size) {
    const float* h  = (const float*)d_in[0];
    const float* W  = (const float*)d_in[1];
    const float* cs = (const float*)d_in[2];
    const float* cb = (const float*)d_in[3];
    float* out = (float*)d_out;

    cudaFuncSetAttribute(router_gemm_softmax_topk,
                         cudaFuncAttributeMaxDynamicSharedMemorySize, SMEM_BYTES);

    int T  = in_sizes[0] / D_DIM;   // 16384
    int nb = T / TM;                // 128 blocks
    router_gemm_softmax_topk<<<nb, NTHREADS, SMEM_BYTES>>>(h, W, cs, cb, out, T);
}

// round 13
// speedup vs baseline: 1.5565x; 1.3351x over previous
#include <cuda_runtime.h>
#include <cstdint>
#include <cstddef>
#include <math.h>

#define D_DIM 2048
#define E_DIM 64
#define TM    128
#define BK    32
#define KHALF 1024
#define NCH   (KHALF / BK)   // 32 chunks per k-half
#define NTHREADS 256
#define TOPK  8

typedef unsigned long long u64;

// smem (floats): A[2][2][BK][TM] = 16384 fl (64KB), then B[2][2][BK][E_DIM] = 8192 fl (32KB)
#define A_FLOATS   (2 * 2 * BK * TM)
#define SMEM_BYTES ((A_FLOATS + 2 * 2 * BK * E_DIM) * 4)   // 98304

// Packed dual ops (Blackwell f32x2)
__device__ __forceinline__ u64 ffma2(u64 a, u64 b, u64 c) {
    u64 d;
    asm("fma.rn.f32x2 %0, %1, %2, %3;" : "=l"(d) : "l"(a), "l"(b), "l"(c));
    return d;
}
__device__ __forceinline__ u64 fmul2(u64 a, u64 b) {
    u64 d;
    asm("mul.rn.f32x2 %0, %1, %2;" : "=l"(d) : "l"(a), "l"(b));
    return d;
}
__device__ __forceinline__ u64 fadd2(u64 a, u64 b) {
    u64 d;
    asm("add.rn.f32x2 %0, %1, %2;" : "=l"(d) : "l"(a), "l"(b));
    return d;
}
__device__ __forceinline__ u64 dup_f32(float v) {
    unsigned int u = __float_as_uint(v);
    return ((u64)u << 32) | (u64)u;
}

__global__ __launch_bounds__(NTHREADS, 1)
void router_gemm_softmax_topk(const float* __restrict__ h,
                              const float* __restrict__ W,
                              const float* __restrict__ cal_scale,
                              const float* __restrict__ cal_bias,
                              float* __restrict__ out,
                              int T) {
    extern __shared__ float smf[];
    float* Abase = smf;                       // [half][buf][k][128] token-quads swizzled
    float* Bbase = smf + A_FLOATS;            // [half][buf][k][64]  expert-quads swizzled
    float (*P)[TM][E_DIM + 1] = reinterpret_cast<float (*)[TM][E_DIM + 1]>(smf);

    const int tid  = threadIdx.x;
    const int half = tid >> 7;    // k-half
    const int ht   = tid & 127;
    const int s    = ht & 15;     // token slot: tokens 8s..8s+7
    const int eg   = ht >> 4;     // expert group 0..7: experts 8eg..8eg+7
    const int t0   = blockIdx.x * TM;

    // coalesced-loader roles: 8 lanes per row, lane covers 16B of the row chunk
    const int lr = ht >> 3;       // row-within-16-group (0..15)
    const int lc = ht & 7;        // quad column within chunk (0..7) -> k = 4*lc+j
    const int ar = lr & 3;        // row % 4
    const int aq = lr >> 2;       // row quad base contribution (0..3)

    const float* hbase = h + (size_t)(t0 + lr) * D_DIM + half * KHALF + 4 * lc;
    const float* wbase = W + (size_t)lr * D_DIM + half * KHALF + 4 * lc;

    // accumulators: 4 token-pairs x 8 experts (this k-half)
    u64 acc[4][8];
#pragma unroll
    for (int j = 0; j < 4; j++)
#pragma unroll
        for (int i = 0; i < 8; i++) acc[j][i] = 0ULL;

    float4 a4[8];   // 8 row-segments of A (rows lr, lr+16, ..., lr+112)
    float4 b4[4];   // 4 row-segments of B (rows lr, lr+16, lr+32, lr+48)

    auto ldg_chunk = [&](int c) {
#pragma unroll
        for (int it = 0; it < 8; it++)
            a4[it] = *reinterpret_cast<const float4*>(
                hbase + (size_t)it * 16 * D_DIM + c * BK);
#pragma unroll
        for (int it = 0; it < 4; it++)
            b4[it] = *reinterpret_cast<const float4*>(
                wbase + (size_t)it * 16 * D_DIM + c * BK);
    };

    // swizzled transpose-store: A[k][quad'] with quad' = (tok>>2) ^ (k>>2); k>>2 == lc here
    auto sts_chunk = [&](int buf) {
        float* Ab = Abase + (size_t)(half * 2 + buf) * BK * TM + (4 * lc) * TM;
        float* Bb = Bbase + (size_t)(half * 2 + buf) * BK * E_DIM + (4 * lc) * E_DIM;
#pragma unroll
        for (int it = 0; it < 8; it++) {
            const int q2 = (it * 4 + aq) ^ lc;
            float* dst = Ab + 4 * q2 + ar;
            dst[0 * TM] = a4[it].x;
            dst[1 * TM] = a4[it].y;
            dst[2 * TM] = a4[it].z;
            dst[3 * TM] = a4[it].w;
        }
#pragma unroll
        for (int it = 0; it < 4; it++) {
            const int q2 = (it * 4 + aq) ^ lc;
            float* dst = Bb + 4 * q2 + ar;
            dst[0 * E_DIM] = b4[it].x;
            dst[1 * E_DIM] = b4[it].y;
            dst[2 * E_DIM] = b4[it].z;
            dst[3 * E_DIM] = b4[it].w;
        }
    };

    // prologue
    ldg_chunk(0);
    sts_chunk(0);
    __syncthreads();

    for (int c = 0; c < NCH; c++) {
        const int buf = c & 1;
        if (c + 1 < NCH) ldg_chunk(c + 1);

        const float* Ab = Abase + (size_t)(half * 2 + buf) * BK * TM;
        const float* Bb = Bbase + (size_t)(half * 2 + buf) * BK * E_DIM;

        // level-1: plain 32-deep FMA2 chain per accumulator (chunk partial)
        u64 y[4][8];
#pragma unroll
        for (int k = 0; k < BK; k++) {
            const int ksw = k >> 2;
            const float* Ak = Ab + k * TM;
            const float* Bk = Bb + k * E_DIM;
            ulonglong2 aA = *reinterpret_cast<const ulonglong2*>(
                Ak + 4 * ((2 * s) ^ ksw));          // tokens 8s..8s+3
            ulonglong2 aB = *reinterpret_cast<const ulonglong2*>(
                Ak + 4 * ((2 * s + 1) ^ ksw));      // tokens 8s+4..8s+7
            u64 a[4] = {aA.x, aA.y, aB.x, aB.y};
            float4 bf0 = *reinterpret_cast<const float4*>(
                Bk + 4 * ((2 * eg) ^ ksw));         // experts 8eg..8eg+3
            float4 bf1 = *reinterpret_cast<const float4*>(
                Bk + 4 * ((2 * eg + 1) ^ ksw));     // experts 8eg+4..8eg+7
            u64 bd[8] = {dup_f32(bf0.x), dup_f32(bf0.y),
                         dup_f32(bf0.z), dup_f32(bf0.w),
                         dup_f32(bf1.x), dup_f32(bf1.y),
                         dup_f32(bf1.z), dup_f32(bf1.w)};
            if (k == 0) {
#pragma unroll
                for (int j = 0; j < 4; j++)
#pragma unroll
                    for (int i = 0; i < 8; i++)
                        y[j][i] = fmul2(a[j], bd[i]);
            } else {
#pragma unroll
                for (int j = 0; j < 4; j++)
#pragma unroll
                    for (int i = 0; i < 8; i++)
                        y[j][i] = ffma2(a[j], bd[i], y[j][i]);
            }
        }
        // level-2 cascade
#pragma unroll
        for (int j = 0; j < 4; j++)
#pragma unroll
            for (int i = 0; i < 8; i++)
                acc[j][i] = fadd2(acc[j][i], y[j][i]);

        if (c + 1 < NCH) sts_chunk(buf ^ 1);   // other buffer: safe vs current reads
        __syncthreads();
    }

    // ---- dump raw half-partials (tile region dead after last sync) ----
#pragma unroll
    for (int j = 0; j < 4; j++) {
        int tA = 8 * s + 2 * j;   // pair j -> tokens tA, tA+1
#pragma unroll
        for (int i = 0; i < 8; i++) {
            u64 v = acc[j][i];
            P[half][tA + 0][8 * eg + i] =
                __uint_as_float((unsigned int)(v & 0xffffffffULL));
            P[half][tA + 1][8 * eg + i] =
                __uint_as_float((unsigned int)(v >> 32));
        }
    }
    __syncthreads();

    // ---- per-token: combine halves, calibrate, softmax + top-8 ----
    if (tid < TM) {
        const int t = tid;
        const float* r1 = P[1][t];
        float* row = P[0][t];
#pragma unroll 8
        for (int ee = 0; ee < E_DIM; ee++)
            row[ee] = fmaf(row[ee] + r1[ee], cal_scale[ee], cal_bias[ee]);

        float m = row[0];
#pragma unroll 8
        for (int ee = 1; ee < E_DIM; ee++) m = fmaxf(m, row[ee]);
        float ssum = 0.0f;
#pragma unroll 8
        for (int ee = 0; ee < E_DIM; ee++) {
            float p = expf(row[ee] - m);
            row[ee] = p;
            ssum += p;
        }
        float inv = 1.0f / ssum;
        float* oprob = out + (size_t)(t0 + t) * E_DIM;
#pragma unroll 8
        for (int ee = 0; ee < E_DIM; ee++) {
            float p = row[ee] * inv;
            row[ee] = p;
            oprob[ee] = p;
        }

        const size_t base_w = (size_t)T * E_DIM;
        const size_t base_i = base_w + (size_t)T * TOPK;
        u64 used = 0ULL;
#pragma unroll
        for (int rr = 0; rr < TOPK; rr++) {
            float bv = -1.0f;
            int   bi = 0;
            for (int ee = 0; ee < E_DIM; ee++) {
                bool ok = !((used >> ee) & 1ULL);
                float p = row[ee];
                if (ok && p > bv) { bv = p; bi = ee; }
            }
            used |= 1ULL << bi;
            out[base_w + (size_t)(t0 + t) * TOPK + rr] = bv;
            out[base_i + (size_t)(t0 + t) * TOPK + rr] = (float)bi;
        }
    }
}

extern "C" void kernel_launch(void* const* d_in, const int* in_sizes, int n_in,
                              void* d_out, int out_size) {
    const float* h  = (const float*)d_in[0];
    const float* W  = (const float*)d_in[1];
    const float* cs = (const float*)d_in[2];
    const float* cb = (const float*)d_in[3];
    float* out = (float*)d_out;

    cudaFuncSetAttribute(router_gemm_softmax_topk,
                         cudaFuncAttributeMaxDynamicSharedMemorySize, SMEM_BYTES);

    int T  = in_sizes[0] / D_DIM;   // 16384
    int nb = T / TM;                // 128 blocks
    router_gemm_softmax_topk<<<nb, NTHREADS, SMEM_BYTES>>>(h, W, cs, cb, out, T);
}

// round 14
// speedup vs baseline: 1.6616x; 1.0675x over previous
#include <cuda_runtime.h>
#include <cstdint>
#include <cstddef>
#include <math.h>

#define D_DIM 2048
#define E_DIM 64
#define TM    128
#define BK    32
#define KHALF 1024
#define NCH   (KHALF / BK)   // 32 chunks per k-half
#define NTHREADS 256
#define TOPK  8

typedef unsigned long long u64;

// smem (floats): A[2][2][BK][TM] = 16384 fl (64KB), then B[2][2][BK][E_DIM] = 8192 fl (32KB)
#define A_FLOATS   (2 * 2 * BK * TM)
#define SMEM_BYTES ((A_FLOATS + 2 * 2 * BK * E_DIM) * 4)   // 98304

// Packed dual ops (Blackwell f32x2)
__device__ __forceinline__ u64 ffma2(u64 a, u64 b, u64 c) {
    u64 d;
    asm("fma.rn.f32x2 %0, %1, %2, %3;" : "=l"(d) : "l"(a), "l"(b), "l"(c));
    return d;
}
__device__ __forceinline__ u64 fmul2(u64 a, u64 b) {
    u64 d;
    asm("mul.rn.f32x2 %0, %1, %2;" : "=l"(d) : "l"(a), "l"(b));
    return d;
}
__device__ __forceinline__ u64 fadd2(u64 a, u64 b) {
    u64 d;
    asm("add.rn.f32x2 %0, %1, %2;" : "=l"(d) : "l"(a), "l"(b));
    return d;
}
__device__ __forceinline__ u64 dup_f32(float v) {
    unsigned int u = __float_as_uint(v);
    return ((u64)u << 32) | (u64)u;
}

__global__ __launch_bounds__(NTHREADS, 1)
void router_gemm_softmax_topk(const float* __restrict__ h,
                              const float* __restrict__ W,
                              const float* __restrict__ cal_scale,
                              const float* __restrict__ cal_bias,
                              float* __restrict__ out,
                              int T) {
    extern __shared__ float smf[];
    float* Abase = smf;                       // [half][buf][k][128] token-quads swizzled
    float* Bbase = smf + A_FLOATS;            // [half][buf][k][64]  expert-quads swizzled
    float (*P)[TM][E_DIM + 1] = reinterpret_cast<float (*)[TM][E_DIM + 1]>(smf);

    const int tid  = threadIdx.x;
    const int half = tid >> 7;    // k-half
    const int ht   = tid & 127;
    const int s    = ht & 15;     // token slot: tokens 4s..4s+3 and 64+4s..64+4s+3
    const int eg   = ht >> 4;     // expert group 0..7: experts 8eg..8eg+7
    const int t0   = blockIdx.x * TM;

    // coalesced-loader roles: 8 lanes per row, lane covers 16B of the row chunk
    const int lr = ht >> 3;       // row-within-16-group (0..15)
    const int lc = ht & 7;        // quad column within chunk (0..7) -> k = 4*lc+j
    const int ar = lr & 3;        // row % 4
    const int aq = lr >> 2;       // row quad base contribution (0..3)

    const float* hbase = h + (size_t)(t0 + lr) * D_DIM + half * KHALF + 4 * lc;
    const float* wbase = W + (size_t)lr * D_DIM + half * KHALF + 4 * lc;

    // accumulators: 4 token-pairs x 8 experts (this k-half)
    u64 acc[4][8];
#pragma unroll
    for (int j = 0; j < 4; j++)
#pragma unroll
        for (int i = 0; i < 8; i++) acc[j][i] = 0ULL;

    float4 a4[8];   // 8 row-segments of A (rows lr, lr+16, ..., lr+112)
    float4 b4[4];   // 4 row-segments of B (rows lr, lr+16, lr+32, lr+48)

    auto ldg_chunk = [&](int c) {
#pragma unroll
        for (int it = 0; it < 8; it++)
            a4[it] = *reinterpret_cast<const float4*>(
                hbase + (size_t)it * 16 * D_DIM + c * BK);
#pragma unroll
        for (int it = 0; it < 4; it++)
            b4[it] = *reinterpret_cast<const float4*>(
                wbase + (size_t)it * 16 * D_DIM + c * BK);
    };

    // swizzled transpose-store: row r at physical quad (r>>2)^(k>>2); k>>2 == lc here
    auto sts_chunk = [&](int buf) {
        float* Ab = Abase + (size_t)(half * 2 + buf) * BK * TM + (4 * lc) * TM;
        float* Bb = Bbase + (size_t)(half * 2 + buf) * BK * E_DIM + (4 * lc) * E_DIM;
#pragma unroll
        for (int it = 0; it < 8; it++) {
            const int q2 = (it * 4 + aq) ^ lc;
            float* dst = Ab + 4 * q2 + ar;
            dst[0 * TM] = a4[it].x;
            dst[1 * TM] = a4[it].y;
            dst[2 * TM] = a4[it].z;
            dst[3 * TM] = a4[it].w;
        }
#pragma unroll
        for (int it = 0; it < 4; it++) {
            const int q2 = (it * 4 + aq) ^ lc;
            float* dst = Bb + 4 * q2 + ar;
            dst[0 * E_DIM] = b4[it].x;
            dst[1 * E_DIM] = b4[it].y;
            dst[2 * E_DIM] = b4[it].z;
            dst[3 * E_DIM] = b4[it].w;
        }
    };

    // prologue
    ldg_chunk(0);
    sts_chunk(0);
    __syncthreads();

    for (int c = 0; c < NCH; c++) {
        const int buf = c & 1;
        if (c + 1 < NCH) ldg_chunk(c + 1);

        const float* Ab = Abase + (size_t)(half * 2 + buf) * BK * TM;
        const float* Bb = Bbase + (size_t)(half * 2 + buf) * BK * E_DIM;

        // level-1: plain 32-deep FMA2 chain per accumulator (chunk partial)
        u64 y[4][8];
#pragma unroll
        for (int k = 0; k < BK; k++) {
            const int ksw = k >> 2;
            const float* Ak = Ab + k * TM;
            const float* Bk = Bb + k * E_DIM;
            // conflict-free: phase lanes (s=0..7) read quads s^ksw — distinct mod 8
            ulonglong2 aA = *reinterpret_cast<const ulonglong2*>(
                Ak + 4 * (s ^ ksw));                // tokens 4s..4s+3
            ulonglong2 aB = *reinterpret_cast<const ulonglong2*>(
                Ak + 4 * (16 + (s ^ ksw)));         // tokens 64+4s..64+4s+3
            u64 a[4] = {aA.x, aA.y, aB.x, aB.y};
            float4 bf0 = *reinterpret_cast<const float4*>(
                Bk + 4 * ((2 * eg) ^ ksw));         // experts 8eg..8eg+3
            float4 bf1 = *reinterpret_cast<const float4*>(
                Bk + 4 * ((2 * eg + 1) ^ ksw));     // experts 8eg+4..8eg+7
            u64 bd[8] = {dup_f32(bf0.x), dup_f32(bf0.y),
                         dup_f32(bf0.z), dup_f32(bf0.w),
                         dup_f32(bf1.x), dup_f32(bf1.y),
                         dup_f32(bf1.z), dup_f32(bf1.w)};
            if (k == 0) {
#pragma unroll
                for (int j = 0; j < 4; j++)
#pragma unroll
                    for (int i = 0; i < 8; i++)
                        y[j][i] = fmul2(a[j], bd[i]);
            } else {
#pragma unroll
                for (int j = 0; j < 4; j++)
#pragma unroll
                    for (int i = 0; i < 8; i++)
                        y[j][i] = ffma2(a[j], bd[i], y[j][i]);
            }
        }
        // level-2 cascade
#pragma unroll
        for (int j = 0; j < 4; j++)
#pragma unroll
            for (int i = 0; i < 8; i++)
                acc[j][i] = fadd2(acc[j][i], y[j][i]);

        if (c + 1 < NCH) sts_chunk(buf ^ 1);   // other buffer: safe vs current reads
        __syncthreads();
    }

    // ---- dump raw half-partials (tile region dead after last sync) ----
#pragma unroll
    for (int j = 0; j < 4; j++) {
        // pair j -> tokens: j=0:{4s,4s+1} j=1:{4s+2,4s+3} j=2:{64+4s,64+4s+1} j=3:{64+4s+2,+3}
        int tA = ((j & 2) ? 64 : 0) + 4 * s + 2 * (j & 1);
#pragma unroll
        for (int i = 0; i < 8; i++) {
            u64 v = acc[j][i];
            P[half][tA + 0][8 * eg + i] =
                __uint_as_float((unsigned int)(v & 0xffffffffULL));
            P[half][tA + 1][8 * eg + i] =
                __uint_as_float((unsigned int)(v >> 32));
        }
    }
    __syncthreads();

    // ---- per-token: combine halves, calibrate, softmax + top-8 ----
    if (tid < TM) {
        const int t = tid;
        const float* r1 = P[1][t];
        float* row = P[0][t];
#pragma unroll 8
        for (int ee = 0; ee < E_DIM; ee++)
            row[ee] = fmaf(row[ee] + r1[ee], cal_scale[ee], cal_bias[ee]);

        float m = row[0];
#pragma unroll 8
        for (int ee = 1; ee < E_DIM; ee++) m = fmaxf(m, row[ee]);
        float ssum = 0.0f;
#pragma unroll 8
        for (int ee = 0; ee < E_DIM; ee++) {
            float p = expf(row[ee] - m);
            row[ee] = p;
            ssum += p;
        }
        float inv = 1.0f / ssum;
        float* oprob = out + (size_t)(t0 + t) * E_DIM;
#pragma unroll 8
        for (int ee = 0; ee < E_DIM; ee++) {
            float p = row[ee] * inv;
            row[ee] = p;
            oprob[ee] = p;
        }

        const size_t base_w = (size_t)T * E_DIM;
        const size_t base_i = base_w + (size_t)T * TOPK;
        u64 used = 0ULL;
#pragma unroll
        for (int rr = 0; rr < TOPK; rr++) {
            float bv = -1.0f;
            int   bi = 0;
            for (int ee = 0; ee < E_DIM; ee++) {
                bool ok = !((used >> ee) & 1ULL);
                float p = row[ee];
                if (ok && p > bv) { bv = p; bi = ee; }
            }
            used |= 1ULL << bi;
            out[base_w + (size_t)(t0 + t) * TOPK + rr] = bv;
            out[base_i + (size_t)(t0 + t) * TOPK + rr] = (float)bi;
        }
    }
}

extern "C" void kernel_launch(void* const* d_in, const int* in_sizes, int n_in,
                              void* d_out, int out_size) {
    const float* h  = (const float*)d_in[0];
    const float* W  = (const float*)d_in[1];
    const float* cs = (const float*)d_in[2];
    const float* cb = (const float*)d_in[3];
    float* out = (float*)d_out;

    cudaFuncSetAttribute(router_gemm_softmax_topk,
                         cudaFuncAttributeMaxDynamicSharedMemorySize, SMEM_BYTES);

    int T  = in_sizes[0] / D_DIM;   // 16384
    int nb = T / TM;                // 128 blocks
    router_gemm_softmax_topk<<<nb, NTHREADS, SMEM_BYTES>>>(h, W, cs, cb, out, T);
}